// round 14
// baseline (speedup 1.0000x reference)
#include <cuda_runtime.h>
#include <math.h>
#include <stdint.h>

// Shape fixed by reference: [4,1,128,256,256] fp32
#define IMG_W    256
#define IMG_H    256
#define NSLICES  512                  // B*D
#define STRIP_H  64                   // rows per block
#define STRIPS   (IMG_H / STRIP_H)    // 4
#define NB       (NSLICES * STRIPS)   // 2048 blocks
#define NSTEPS   (STRIP_H / 2)        // 32 (2 output rows per step)
#define LASTPAIR NSTEPS               // row-pairs 0..32 per strip
#define NSTAGE   5                    // ring stages (row-pairs in flight)
#define ROWF     260                  // padded floats per smem row (16B-aligned slots)
#define STAGEF   (4 * ROWF)           // PA, PB, TA, TB rows per stage
#define N_TOTAL  (4.0 * 128.0 * 256.0 * 256.0)

__device__ float        g_partials[NB];
__device__ unsigned int g_count = 0;

__device__ __forceinline__ float sqrt_approx(float x) {
    float r; asm("sqrt.approx.f32 %0, %1;" : "=f"(r) : "f"(x)); return r;
}

// Separable row aggregate for one column from a smem row:
//   h1 = r - l        (ex = h1[y-1] + 2h1[y] + h1[y+1])
//   h2 = l + 2m + r   (ey = h2[y+1] - h2[y-1])
__device__ __forceinline__ void agg_from(const float* __restrict__ row, int c,
                                         bool hl, bool hr, float& h1, float& h2)
{
    const float m = row[c];
    const float l = hl ? row[c - 1] : 0.f;
    const float r = hr ? row[c + 1] : 0.f;
    h1 = r - l;
    h2 = fmaf(2.f, m, l + r);
}

__global__ __launch_bounds__(256, 6)
void edge_loss_kernel(const float* __restrict__ pred,
                      const float* __restrict__ target,
                      float* __restrict__ out)
{
    __shared__ float ring[NSTAGE * STAGEF];   // ~20.8 KB row ring
    __shared__ float warp_sums[8];
    __shared__ int   s_last;

    const int tid  = threadIdx.x;             // owns image column `tid`
    const int q    = tid >> 6;                // loader quarter: 0=PA 1=PB 2=TA 3=TB
    const int c4   = (tid & 63) << 2;         // loader col base (16B chunks)
    const int lane = tid & 31;
    const bool has_l = (tid != 0);
    const bool has_r = (tid != 255);

    const int r0 = blockIdx.x * STRIP_H;
    const size_t base = (size_t)blockIdx.y * (IMG_H * IMG_W);
    const float* __restrict__ gimg =
        ((q < 2) ? pred : target) + base;     // this thread's loader image
    const int rowadd = q & 1;                 // A or B row of the pair

    // ---- Prologue: issue row-pairs 0..3 into stages 0..3 ----
    #pragma unroll
    for (int p = 0; p < 4; p++) {
        const int myrow = (r0 - 1 + 2 * p) + rowadd;
        const uint32_t sa = (uint32_t)__cvta_generic_to_shared(
            &ring[p * STAGEF + q * ROWF + c4]);
        if (myrow >= 0 && myrow < IMG_H) {
            const float* g = gimg + myrow * IMG_W + c4;
            asm volatile("cp.async.cg.shared.global [%0], [%1], 16;"
                         :: "r"(sa), "l"(g));
        } else {
            asm volatile("st.shared.v4.b32 [%0], {%1,%1,%1,%1};"
                         :: "r"(sa), "r"(0u));
        }
        asm volatile("cp.async.commit_group;");
    }

    asm volatile("cp.async.wait_group 3;");   // pair 0 landed
    __syncthreads();

    // ---- Prologue aggregates from stage 0: rows r0-1 (A), r0 (B) ----
    float ph1p, ph2p, ph1c, ph2c, th1p, th2p, th1c, th2c;
    agg_from(&ring[0 * ROWF], tid, has_l, has_r, ph1p, ph2p);
    agg_from(&ring[1 * ROWF], tid, has_l, has_r, ph1c, ph2c);
    agg_from(&ring[2 * ROWF], tid, has_l, has_r, th1p, th2p);
    agg_from(&ring[3 * ROWF], tid, has_l, has_r, th1c, th2c);

    float acc = 0.f;
    int s_wr = 4;   // stage receiving pair k+4
    int s_rd = 1;   // stage holding pair k+1

    #pragma unroll 1
    for (int k = 0; k < NSTEPS; k++) {
        // Issue pair k+4 (stage s_wr: its old pair was consumed 2 bars ago).
        if (k + 4 <= LASTPAIR) {
            const int myrow = (r0 - 1 + 2 * (k + 4)) + rowadd;
            const uint32_t sa = (uint32_t)__cvta_generic_to_shared(
                &ring[s_wr * STAGEF + q * ROWF + c4]);
            if (myrow >= 0 && myrow < IMG_H) {
                const float* g = gimg + myrow * IMG_W + c4;
                asm volatile("cp.async.cg.shared.global [%0], [%1], 16;"
                             :: "r"(sa), "l"(g));
            } else {
                asm volatile("st.shared.v4.b32 [%0], {%1,%1,%1,%1};"
                             :: "r"(sa), "r"(0u));
            }
        }
        asm volatile("cp.async.commit_group;"); // empty group when skipped
        asm volatile("cp.async.wait_group 3;"); // pair k+1 landed (own groups)
        __syncthreads();                        // ...and visible to all threads

        // New rows A = r0+2k+1, B = r0+2k+2 from stage s_rd
        const float* st = &ring[s_rd * STAGEF];
        float ph1a, ph2a, ph1b, ph2b, th1a, th2a, th1b, th2b;
        agg_from(st + 0 * ROWF, tid, has_l, has_r, ph1a, ph2a);
        agg_from(st + 1 * ROWF, tid, has_l, has_r, ph1b, ph2b);
        agg_from(st + 2 * ROWF, tid, has_l, has_r, th1a, th2a);
        agg_from(st + 3 * ROWF, tid, has_l, has_r, th1b, th2b);

        // Output row r0+2k   (window: prev, cur, A)
        {
            float ex = fmaf(2.f, ph1c, ph1p) + ph1a;
            float ey = ph2a - ph2p;
            const float mp = sqrt_approx(fmaf(ex, ex, fmaf(ey, ey, 1e-8f)));
            ex = fmaf(2.f, th1c, th1p) + th1a;
            ey = th2a - th2p;
            const float mt = sqrt_approx(fmaf(ex, ex, fmaf(ey, ey, 1e-8f)));
            acc += fabsf(mp - mt);
        }
        // Output row r0+2k+1 (window: cur, A, B)
        {
            float ex = fmaf(2.f, ph1a, ph1c) + ph1b;
            float ey = ph2b - ph2c;
            const float mp = sqrt_approx(fmaf(ex, ex, fmaf(ey, ey, 1e-8f)));
            ex = fmaf(2.f, th1a, th1c) + th1b;
            ey = th2b - th2c;
            const float mt = sqrt_approx(fmaf(ex, ex, fmaf(ey, ey, 1e-8f)));
            acc += fabsf(mp - mt);
        }

        ph1p = ph1a; ph2p = ph2a; ph1c = ph1b; ph2c = ph2b;
        th1p = th1a; th2p = th2a; th1c = th1b; th2c = th2b;

        s_rd = (s_rd == NSTAGE - 1) ? 0 : s_rd + 1;
        s_wr = (s_wr == NSTAGE - 1) ? 0 : s_wr + 1;
    }

    // ---- Deterministic block reduction ----
    #pragma unroll
    for (int offr = 16; offr > 0; offr >>= 1)
        acc += __shfl_down_sync(0xffffffffu, acc, offr);
    if (lane == 0) warp_sums[tid >> 5] = acc;
    __syncthreads();

    if (tid == 0) {
        float s = 0.f;
        #pragma unroll
        for (int i = 0; i < 8; i++) s += warp_sums[i];
        g_partials[blockIdx.y * gridDim.x + blockIdx.x] = s;
        __threadfence();
        const unsigned old = atomicAdd(&g_count, 1u);
        s_last = (old == NB - 1) ? 1 : 0;
    }
    __syncthreads();

    // ---- Last block: deterministic final reduce (fixed order, double) ----
    if (s_last) {
        __shared__ double dred[256];
        double s = 0.0;
        #pragma unroll 8
        for (int i = tid; i < NB; i += 256)
            s += (double)g_partials[i];
        dred[tid] = s;
        __syncthreads();
        #pragma unroll
        for (int offr = 128; offr > 0; offr >>= 1) {
            if (tid < offr) dred[tid] += dred[tid + offr];
            __syncthreads();
        }
        if (tid == 0) {
            out[0]  = (float)(dred[0] / N_TOTAL);
            g_count = 0;   // reset for next graph replay
        }
    }
}

extern "C" void kernel_launch(void* const* d_in, const int* in_sizes, int n_in,
                              void* d_out, int out_size)
{
    (void)in_sizes; (void)n_in; (void)out_size;
    const float* pred   = (const float*)d_in[0];
    const float* target = (const float*)d_in[1];
    float* out = (float*)d_out;

    dim3 grid(STRIPS, NSLICES);   // 4 x 512 = 2048 blocks
    edge_loss_kernel<<<grid, 256>>>(pred, target, out);
}

// round 15
// speedup vs baseline: 1.0724x; 1.0724x over previous
#include <cuda_runtime.h>
#include <math.h>

// Shape fixed by reference: [4,1,128,256,256] fp32
#define IMG_W    256
#define IMG_H    256
#define NSLICES  512                  // B*D
#define STRIP_H  64                   // rows per block
#define STRIPS   (IMG_H / STRIP_H)    // 4
#define NB       (NSLICES * STRIPS)   // 2048 blocks
#define YT       4                    // y groups (256 thr = 64 x * 4 y)
#define NR       (STRIP_H / YT)       // 16 output rows per thread
#define N_TOTAL  (4.0 * 128.0 * 256.0 * 256.0)
#define ROW_BYTES (IMG_W * 4)

__device__ float        g_partials[NB];
__device__ unsigned int g_count = 0;

__device__ __forceinline__ float sqrt_approx(float x) {
    float r; asm("sqrt.approx.f32 %0, %1;" : "=f"(r) : "f"(x)); return r;
}

struct Row6 { float n0, n1, n2, n3, n4, n5; };  // cols [cb-1 .. cb+4]

// Raw loads only: one aligned float4 + two independent halo scalars
// (L1 hits — same 128B lines as neighboring lanes' vectors).
// No shuffles, no convergence points; all LDGs independent -> high MLP.
__device__ __forceinline__ Row6 load_row(const float* __restrict__ base,
                                         int byte_off,
                                         bool row_ok, bool has_l, bool has_r)
{
    const float* p = (const float*)((const char*)base + byte_off);
    Row6 o;
    float4 v = make_float4(0.f, 0.f, 0.f, 0.f);
    float  l = 0.f, r = 0.f;
    if (row_ok) {
        v = *reinterpret_cast<const float4*>(p);
        if (has_l) l = p[-1];
        if (has_r) r = p[4];
    }
    o.n0 = l; o.n1 = v.x; o.n2 = v.y; o.n3 = v.z; o.n4 = v.w; o.n5 = r;
    return o;
}

// Separable row aggregates for 4 columns:
//   h1 = r - l        (ex = h1[y-1] + 2h1[y] + h1[y+1])
//   h2 = l + 2m + r   (ey = h2[y+1] - h2[y-1])
__device__ __forceinline__ void row_agg(const Row6& n, float h1[4], float h2[4])
{
    h1[0] = n.n2 - n.n0;  h2[0] = fmaf(2.f, n.n1, n.n0 + n.n2);
    h1[1] = n.n3 - n.n1;  h2[1] = fmaf(2.f, n.n2, n.n1 + n.n3);
    h1[2] = n.n4 - n.n2;  h2[2] = fmaf(2.f, n.n3, n.n2 + n.n4);
    h1[3] = n.n5 - n.n3;  h2[3] = fmaf(2.f, n.n4, n.n3 + n.n5);
}

__global__ __launch_bounds__(256, 4)
void edge_loss_kernel(const float* __restrict__ pred,
                      const float* __restrict__ target,
                      float* __restrict__ out)
{
    __shared__ float warp_sums[8];
    __shared__ int   s_last;

    const int tid  = threadIdx.x;
    const int x    = tid & 63;            // 0..63 -> cols [4x, 4x+3]
    const int ty   = tid >> 6;            // 0..3
    const int lane = tid & 31;
    const int cb   = x << 2;
    const bool has_l = (x != 0);
    const bool has_r = (x != 63);

    const int r0 = blockIdx.x * STRIP_H + ty * NR;

    const size_t base = (size_t)blockIdx.y * (IMG_H * IMG_W);
    const float* __restrict__ P = pred + base + cb + (size_t)r0 * IMG_W;
    const float* __restrict__ T = target + base + cb + (size_t)r0 * IMG_W;

    float ph1p[4], ph2p[4], ph1c[4], ph2c[4];
    float th1p[4], th2p[4], th1c[4], th2c[4];

    // Prologue: rows r0-1 and r0
    {
        const Row6 pp = load_row(P, -ROW_BYTES, r0 > 0, has_l, has_r);
        const Row6 tp = load_row(T, -ROW_BYTES, r0 > 0, has_l, has_r);
        const Row6 pc = load_row(P, 0, true, has_l, has_r);
        const Row6 tc = load_row(T, 0, true, has_l, has_r);
        row_agg(pp, ph1p, ph2p);
        row_agg(tp, th1p, th2p);
        row_agg(pc, ph1c, ph2c);
        row_agg(tc, th1c, th2c);
    }

    // Prefetch first body row (r0+1); off tracks the prefetched row
    int off = ROW_BYTES;
    Row6 pcur = load_row(P, off, r0 + 1 < IMG_H, has_l, has_r);
    Row6 tcur = load_row(T, off, r0 + 1 < IMG_H, has_l, has_r);

    float acc = 0.f;

    #pragma unroll
    for (int i = 0; i < NR; i++) {
        // Prefetch row r0+2+i while computing on (pcur, tcur)
        const bool nok = (r0 + 2 + i < IMG_H);
        off += ROW_BYTES;
        const Row6 pnxt = load_row(P, off, nok, has_l, has_r);
        const Row6 tnxt = load_row(T, off, nok, has_l, has_r);

        float ph1n[4], ph2n[4], th1n[4], th2n[4];
        row_agg(pcur, ph1n, ph2n);
        row_agg(tcur, th1n, th2n);

        #pragma unroll
        for (int j = 0; j < 4; j++) {
            float ex = fmaf(2.f, ph1c[j], ph1p[j]) + ph1n[j];
            float ey = ph2n[j] - ph2p[j];
            const float magp = sqrt_approx(fmaf(ex, ex, fmaf(ey, ey, 1e-8f)));

            ex = fmaf(2.f, th1c[j], th1p[j]) + th1n[j];
            ey = th2n[j] - th2p[j];
            const float magt = sqrt_approx(fmaf(ex, ex, fmaf(ey, ey, 1e-8f)));

            acc += fabsf(magp - magt);
        }

        #pragma unroll
        for (int j = 0; j < 4; j++) {
            ph1p[j] = ph1c[j]; ph1c[j] = ph1n[j];
            ph2p[j] = ph2c[j]; ph2c[j] = ph2n[j];
            th1p[j] = th1c[j]; th1c[j] = th1n[j];
            th2p[j] = th2c[j]; th2c[j] = th2n[j];
        }
        pcur = pnxt; tcur = tnxt;
    }

    // ---- Deterministic block reduction ----
    #pragma unroll
    for (int offr = 16; offr > 0; offr >>= 1)
        acc += __shfl_down_sync(0xffffffffu, acc, offr);
    if (lane == 0) warp_sums[tid >> 5] = acc;
    __syncthreads();

    if (tid == 0) {
        float s = 0.f;
        #pragma unroll
        for (int i = 0; i < 8; i++) s += warp_sums[i];
        g_partials[blockIdx.y * gridDim.x + blockIdx.x] = s;
        __threadfence();
        const unsigned old = atomicAdd(&g_count, 1u);
        s_last = (old == NB - 1) ? 1 : 0;
    }
    __syncthreads();

    // ---- Last block: deterministic final reduce (fixed order, double) ----
    if (s_last) {
        __shared__ double dred[256];
        double s = 0.0;
        #pragma unroll 8
        for (int i = tid; i < NB; i += 256)
            s += (double)g_partials[i];
        dred[tid] = s;
        __syncthreads();
        #pragma unroll
        for (int offr = 128; offr > 0; offr >>= 1) {
            if (tid < offr) dred[tid] += dred[tid + offr];
            __syncthreads();
        }
        if (tid == 0) {
            out[0]  = (float)(dred[0] / N_TOTAL);
            g_count = 0;   // reset for next graph replay
        }
    }
}

extern "C" void kernel_launch(void* const* d_in, const int* in_sizes, int n_in,
                              void* d_out, int out_size)
{
    (void)in_sizes; (void)n_in; (void)out_size;
    const float* pred   = (const float*)d_in[0];
    const float* target = (const float*)d_in[1];
    float* out = (float*)d_out;

    dim3 grid(STRIPS, NSLICES);   // 4 x 512 = 2048 blocks
    edge_loss_kernel<<<grid, 256>>>(pred, target, out);
}

// round 16
// speedup vs baseline: 1.4580x; 1.3596x over previous
#include <cuda_runtime.h>
#include <math.h>
#include <stdint.h>

// Shape fixed by reference: [4,1,128,256,256] fp32
#define IMG_W    256
#define IMG_H    256
#define NSLICES  512                   // B*D
#define STRIP_H  32                    // output rows per block
#define STRIPS   (IMG_H / STRIP_H)     // 8
#define NB       (NSLICES * STRIPS)    // 4096 blocks
#define TROWS    (STRIP_H + 2)         // 34 tile rows (with halo)
#define PADF     4                     // left zero-pad floats per smem row
#define ROWF     264                   // smem row stride in floats (16B mult)
#define IMGF     (TROWS * ROWF)        // floats per image tile
#define SMEM_BYTES (2 * IMGF * 4)      // 71808 B
#define NR       8                     // output rows per thread (4 y-groups)
#define N_TOTAL  (4.0 * 128.0 * 256.0 * 256.0)

__device__ float        g_partials[NB];
__device__ unsigned int g_count = 0;

__device__ __forceinline__ float sqrt_approx(float x) {
    float r; asm("sqrt.approx.f32 %0, %1;" : "=f"(r) : "f"(x)); return r;
}

// Row aggregates for 4 columns straight from padded smem (no guards, no SELs):
//   h1 = r - l        (ex = h1[y-1] + 2h1[y] + h1[y+1])
//   h2 = l + 2m + r   (ey = h2[y+1] - h2[y-1])
__device__ __forceinline__ void agg_sm(const float* __restrict__ p,
                                       float h1[4], float h2[4])
{
    const float4 v = *reinterpret_cast<const float4*>(p);   // LDS.128
    const float  l = p[-1];                                 // LDS.32 (pad=0 at edge)
    const float  r = p[4];                                  // LDS.32
    h1[0] = v.y - l;    h2[0] = fmaf(2.f, v.x, l + v.y);
    h1[1] = v.z - v.x;  h2[1] = fmaf(2.f, v.y, v.x + v.z);
    h1[2] = v.w - v.y;  h2[2] = fmaf(2.f, v.z, v.y + v.w);
    h1[3] = r - v.z;    h2[3] = fmaf(2.f, v.w, v.z + r);
}

__global__ __launch_bounds__(256)
void edge_loss_kernel(const float* __restrict__ pred,
                      const float* __restrict__ target,
                      float* __restrict__ out)
{
    extern __shared__ float sm[];          // [2][TROWS][ROWF]
    __shared__ float warp_sums[8];
    __shared__ int   s_last;

    const int tid  = threadIdx.x;
    const int lane = tid & 31;
    const int r0   = blockIdx.x * STRIP_H;
    const size_t base = (size_t)blockIdx.y * (IMG_H * IMG_W);

    // ---- Zero the left/right column pads (once) ----
    for (int idx = tid; idx < 2 * TROWS * 2; idx += 256) {   // 136 chunks
        const int img  = idx & 1;
        const int rem  = idx >> 1;          // 0..67
        const int row  = rem >> 1;          // 0..33
        const int side = rem & 1;
        float* dst = sm + img * IMGF + row * ROWF + (side ? (PADF + IMG_W) : 0);
        *reinterpret_cast<float4*>(dst) = make_float4(0.f, 0.f, 0.f, 0.f);
    }

    // ---- Single-shot bulk fill: 17 cp.async (16B) per thread ----
    // Thread parity picks the image; each (k) step covers 128 chunk-halves.
    const float* __restrict__ gimg = ((tid & 1) ? target : pred) + base;
    const int h0   = tid >> 1;              // 0..127
    const int imgo = (tid & 1) * IMGF;

    #pragma unroll
    for (int k = 0; k < 17; k++) {
        const int half = k * 128 + h0;      // 0..2175
        const int row  = half >> 6;         // 0..33
        const int c16  = half & 63;         // 16B chunk in row
        float* dst = sm + imgo + row * ROWF + PADF + c16 * 4;
        const uint32_t sa = (uint32_t)__cvta_generic_to_shared(dst);
        const int gr = r0 - 1 + row;
        if (gr >= 0 && gr < IMG_H) {
            const float* g = gimg + (size_t)gr * IMG_W + c16 * 4;
            asm volatile("cp.async.cg.shared.global [%0], [%1], 16;"
                         :: "r"(sa), "l"(g));
        } else {
            asm volatile("st.shared.v4.b32 [%0], {%1,%1,%1,%1};"
                         :: "r"(sa), "r"(0u));
        }
    }
    asm volatile("cp.async.commit_group;");
    asm volatile("cp.async.wait_group 0;");
    __syncthreads();

    // ---- Compute phase: pure smem, no guards, no barriers ----
    const int x  = tid & 63;                // col group -> cols [4x, 4x+3]
    const int g  = tid >> 6;                // y group: rows [r0+8g, r0+8g+7]
    const int cb = x << 2;

    const float* P0 = sm + (g * NR) * ROWF + PADF + cb;       // pred, local row 8g
    const float* T0 = P0 + IMGF;

    float pp1[4], pp2[4], pc1[4], pc2[4];
    float tp1[4], tp2[4], tc1[4], tc2[4];
    agg_sm(P0,        pp1, pp2);
    agg_sm(P0 + ROWF, pc1, pc2);
    agg_sm(T0,        tp1, tp2);
    agg_sm(T0 + ROWF, tc1, tc2);

    float acc = 0.f;

    #pragma unroll
    for (int i = 0; i < NR; i++) {
        float pn1[4], pn2[4], tn1[4], tn2[4];
        agg_sm(P0 + (i + 2) * ROWF, pn1, pn2);
        agg_sm(T0 + (i + 2) * ROWF, tn1, tn2);

        #pragma unroll
        for (int j = 0; j < 4; j++) {
            float ex = fmaf(2.f, pc1[j], pp1[j]) + pn1[j];
            float ey = pn2[j] - pp2[j];
            const float magp = sqrt_approx(fmaf(ex, ex, fmaf(ey, ey, 1e-8f)));

            ex = fmaf(2.f, tc1[j], tp1[j]) + tn1[j];
            ey = tn2[j] - tp2[j];
            const float magt = sqrt_approx(fmaf(ex, ex, fmaf(ey, ey, 1e-8f)));

            acc += fabsf(magp - magt);
        }

        #pragma unroll
        for (int j = 0; j < 4; j++) {       // renamed away by full unroll
            pp1[j] = pc1[j]; pc1[j] = pn1[j];
            pp2[j] = pc2[j]; pc2[j] = pn2[j];
            tp1[j] = tc1[j]; tc1[j] = tn1[j];
            tp2[j] = tc2[j]; tc2[j] = tn2[j];
        }
    }

    // ---- Deterministic block reduction ----
    #pragma unroll
    for (int offr = 16; offr > 0; offr >>= 1)
        acc += __shfl_down_sync(0xffffffffu, acc, offr);
    if (lane == 0) warp_sums[tid >> 5] = acc;
    __syncthreads();

    if (tid == 0) {
        float s = 0.f;
        #pragma unroll
        for (int i = 0; i < 8; i++) s += warp_sums[i];
        g_partials[blockIdx.y * gridDim.x + blockIdx.x] = s;
        __threadfence();
        const unsigned old = atomicAdd(&g_count, 1u);
        s_last = (old == NB - 1) ? 1 : 0;
    }
    __syncthreads();

    // ---- Last block: deterministic final reduce (fixed order, double) ----
    if (s_last) {
        __shared__ double dred[256];
        double s = 0.0;
        #pragma unroll 8
        for (int i = tid; i < NB; i += 256)
            s += (double)g_partials[i];
        dred[tid] = s;
        __syncthreads();
        #pragma unroll
        for (int offr = 128; offr > 0; offr >>= 1) {
            if (tid < offr) dred[tid] += dred[tid + offr];
            __syncthreads();
        }
        if (tid == 0) {
            out[0]  = (float)(dred[0] / N_TOTAL);
            g_count = 0;   // reset for next graph replay
        }
    }
}

extern "C" void kernel_launch(void* const* d_in, const int* in_sizes, int n_in,
                              void* d_out, int out_size)
{
    (void)in_sizes; (void)n_in; (void)out_size;
    const float* pred   = (const float*)d_in[0];
    const float* target = (const float*)d_in[1];
    float* out = (float*)d_out;

    cudaFuncSetAttribute(edge_loss_kernel,
                         cudaFuncAttributeMaxDynamicSharedMemorySize, SMEM_BYTES);

    dim3 grid(STRIPS, NSLICES);   // 8 x 512 = 4096 blocks
    edge_loss_kernel<<<grid, 256, SMEM_BYTES>>>(pred, target, out);
}